// round 1
// baseline (speedup 1.0000x reference)
#include <cuda_runtime.h>
#include <math.h>

#define NPTS 160000
#define DIM  128
#define HID  512
#define KK   49
#define PTS  16
#define MBLK 1250   /* NPTS / 128 */

// ---------------- scratch (device globals; no allocations) ----------------
__device__ float g_xln[(size_t)NPTS * DIM];   // LN(dwconv(x))
__device__ float g_h[(size_t)NPTS * HID];     // gelu(xln@w1+b1)
__device__ float g_part[MBLK * HID];          // per-rowblock column sum of h^2
__device__ float g_s[HID];                    // GRN per-channel scale
__device__ float g_x1[(size_t)NPTS * DIM];    // x after depth 0

// ---------------- helpers ----------------
__device__ __forceinline__ float blockSum128(float v, float* sred) {
    #pragma unroll
    for (int o = 16; o > 0; o >>= 1) v += __shfl_down_sync(0xffffffffu, v, o);
    if ((threadIdx.x & 31) == 0) sred[threadIdx.x >> 5] = v;
    __syncthreads();
    float r = sred[0] + sred[1] + sred[2] + sred[3];
    __syncthreads();
    return r;
}

// ---------------- dwconv (sparse 7x7 depthwise) + LayerNorm ----------------
// 128 threads = 128 channels; PTS points per block; weights cached in smem.
__global__ __launch_bounds__(128) void dwconv_ln_kernel(
    const float* __restrict__ feats, const int* __restrict__ nbr,
    const float* __restrict__ w, const float* __restrict__ bdw,
    const float* __restrict__ lg, const float* __restrict__ lb,
    int depth)
{
    __shared__ float sw[KK * DIM];
    __shared__ int   snbr[PTS * KK];
    __shared__ float sred[4];

    const float* X = depth ? g_x1 : feats;
    const int c = threadIdx.x;
    for (int i = c; i < KK * DIM; i += 128) sw[i] = w[i];
    const int n0 = blockIdx.x * PTS;
    for (int i = c; i < PTS * KK; i += 128) snbr[i] = nbr[(size_t)n0 * KK + i];
    const float bd = bdw[c], gg = lg[c], bb = lb[c];
    __syncthreads();

    for (int p = 0; p < PTS; p++) {
        float acc = bd;
        #pragma unroll
        for (int k = 0; k < KK; k++) {
            int idx = snbr[p * KK + k];            // uniform across block
            if (idx < NPTS)                        // idx==NPTS -> zero pad row
                acc += __ldg(X + (size_t)idx * DIM + c) * sw[k * DIM + c];
        }
        float mu  = blockSum128(acc, sred) * (1.0f / DIM);
        float d   = acc - mu;
        float var = blockSum128(d * d, sred) * (1.0f / DIM);
        float y   = d * rsqrtf(var + 1e-6f) * gg + bb;
        g_xln[(size_t)(n0 + p) * DIM + c] = y;
    }
}

// ---------------- GEMM1: h = gelu(xln @ w1 + b1), + colsq partials -------
// 128x128x8 block tile, 8x8 microtile, 256 threads.
__global__ __launch_bounds__(256) void gemm1_gelu_kernel(
    const float* __restrict__ B,     // w1[d]  (DIM, HID)
    const float* __restrict__ bias)  // b1[d]  (HID)
{
    const int K = DIM, Nn = HID;
    __shared__ float smem[2 * 8 * 128];
    float* As = smem;
    float* Bs = smem + 8 * 128;

    const int tid = threadIdx.x;
    const int bx = blockIdx.x, by = blockIdx.y;
    const int tx = tid & 15, ty = tid >> 4;
    const int arow = tid >> 1, acol = (tid & 1) * 4;
    const int brow = tid >> 5, bcol = (tid & 31) * 4;
    const float* Ab = g_xln + (size_t)bx * 128 * K;
    const float* Bb = B + by * 128;

    float acc[8][8] = {};
    for (int k0 = 0; k0 < K; k0 += 8) {
        float4 av = *(const float4*)(Ab + (size_t)arow * K + k0 + acol);
        As[(acol + 0) * 128 + arow] = av.x;
        As[(acol + 1) * 128 + arow] = av.y;
        As[(acol + 2) * 128 + arow] = av.z;
        As[(acol + 3) * 128 + arow] = av.w;
        *(float4*)(Bs + brow * 128 + bcol) =
            *(const float4*)(Bb + (size_t)(k0 + brow) * Nn + bcol);
        __syncthreads();
        #pragma unroll
        for (int kk = 0; kk < 8; kk++) {
            float a[8], b[8];
            #pragma unroll
            for (int i = 0; i < 8; i++) a[i] = As[kk * 128 + ty * 8 + i];
            #pragma unroll
            for (int j = 0; j < 8; j++) b[j] = Bs[kk * 128 + tx * 8 + j];
            #pragma unroll
            for (int i = 0; i < 8; i++)
                #pragma unroll
                for (int j = 0; j < 8; j++)
                    acc[i][j] += a[i] * b[j];
        }
        __syncthreads();
    }

    const int row0 = bx * 128 + ty * 8;
    const int col0 = by * 128 + tx * 8;
    float bia[8];
    #pragma unroll
    for (int j = 0; j < 8; j++) bia[j] = __ldg(bias + col0 + j);

    float colsq[8] = {};
    #pragma unroll
    for (int i = 0; i < 8; i++) {
        float v[8];
        #pragma unroll
        for (int j = 0; j < 8; j++) {
            float t = acc[i][j] + bia[j];
            t = 0.5f * t * (1.0f + erff(t * 0.7071067811865476f));  // exact gelu
            v[j] = t;
            colsq[j] += t * t;
        }
        float4* dst = (float4*)(g_h + (size_t)(row0 + i) * HID + col0);
        dst[0] = make_float4(v[0], v[1], v[2], v[3]);
        dst[1] = make_float4(v[4], v[5], v[6], v[7]);
    }

    // reduce colsq across ty (16 rows of threads) -> one partial per column
    #pragma unroll
    for (int j = 0; j < 8; j++) smem[ty * 128 + tx * 8 + j] = colsq[j];
    __syncthreads();
    if (tid < 128) {
        float s = 0.0f;
        #pragma unroll
        for (int r = 0; r < 16; r++) s += smem[r * 128 + tid];
        g_part[bx * HID + by * 128 + tid] = s;  // unique (bx,by,col): plain store
    }
}

// ---------------- GRN scale finalize: s[j] = grn_g[j]*nx[j] + 1 ----------
__global__ void grn_scale_kernel(const float* __restrict__ grn_g)
{
    const int j = threadIdx.x;   // 512 threads, 1 block
    float sum = 0.0f;
    for (int r = 0; r < MBLK; r++) sum += g_part[r * HID + j];
    float gx = sqrtf(sum);
    __shared__ float sm[HID];
    sm[j] = gx;
    __syncthreads();
    for (int o = 256; o > 0; o >>= 1) {
        if (j < o) sm[j] += sm[j + o];
        __syncthreads();
    }
    float mean = sm[0] * (1.0f / HID);
    g_s[j] = __ldg(grn_g + j) * (gx / (mean + 1e-6f)) + 1.0f;
}

// ---------------- GEMM2: out = (h*s + grn_b) @ w2 + b2 + residual --------
__global__ __launch_bounds__(256) void gemm2_resid_kernel(
    const float* __restrict__ W2,    // w2[d] (HID, DIM)
    const float* __restrict__ b2,    // (DIM)
    const float* __restrict__ gb,    // grn_b[d] (HID)
    const float* __restrict__ feats, // depth-0 residual input
    float* __restrict__ out,         // final output buffer
    int depth)
{
    const int K = HID, Nn = DIM;
    const float* Xin  = depth ? g_x1 : feats;
    float*       Xout = depth ? out  : g_x1;

    __shared__ float smem[2 * 8 * 128];
    float* As = smem;
    float* Bs = smem + 8 * 128;

    const int tid = threadIdx.x;
    const int bx = blockIdx.x;
    const int tx = tid & 15, ty = tid >> 4;
    const int arow = tid >> 1, acol = (tid & 1) * 4;
    const int brow = tid >> 5, bcol = (tid & 31) * 4;
    const float* Ab = g_h + (size_t)bx * 128 * K;

    float acc[8][8] = {};
    for (int k0 = 0; k0 < K; k0 += 8) {
        float4 av = *(const float4*)(Ab + (size_t)arow * K + k0 + acol);
        float4 sv = *(const float4*)(g_s + k0 + acol);
        float4 gv = *(const float4*)(gb + k0 + acol);
        av.x = av.x * sv.x + gv.x;   // GRN affine folded into A-load
        av.y = av.y * sv.y + gv.y;
        av.z = av.z * sv.z + gv.z;
        av.w = av.w * sv.w + gv.w;
        As[(acol + 0) * 128 + arow] = av.x;
        As[(acol + 1) * 128 + arow] = av.y;
        As[(acol + 2) * 128 + arow] = av.z;
        As[(acol + 3) * 128 + arow] = av.w;
        *(float4*)(Bs + brow * 128 + bcol) =
            *(const float4*)(W2 + (size_t)(k0 + brow) * Nn + bcol);
        __syncthreads();
        #pragma unroll
        for (int kk = 0; kk < 8; kk++) {
            float a[8], b[8];
            #pragma unroll
            for (int i = 0; i < 8; i++) a[i] = As[kk * 128 + ty * 8 + i];
            #pragma unroll
            for (int j = 0; j < 8; j++) b[j] = Bs[kk * 128 + tx * 8 + j];
            #pragma unroll
            for (int i = 0; i < 8; i++)
                #pragma unroll
                for (int j = 0; j < 8; j++)
                    acc[i][j] += a[i] * b[j];
        }
        __syncthreads();
    }

    const int row0 = bx * 128 + ty * 8;
    const int col0 = tx * 8;
    float bia[8];
    #pragma unroll
    for (int j = 0; j < 8; j++) bia[j] = __ldg(b2 + col0 + j);

    #pragma unroll
    for (int i = 0; i < 8; i++) {
        const float4* rin = (const float4*)(Xin + (size_t)(row0 + i) * DIM + col0);
        float4 r0 = rin[0], r1 = rin[1];
        float4 o0, o1;
        o0.x = acc[i][0] + bia[0] + r0.x;
        o0.y = acc[i][1] + bia[1] + r0.y;
        o0.z = acc[i][2] + bia[2] + r0.z;
        o0.w = acc[i][3] + bia[3] + r0.w;
        o1.x = acc[i][4] + bia[4] + r1.x;
        o1.y = acc[i][5] + bia[5] + r1.y;
        o1.z = acc[i][6] + bia[6] + r1.z;
        o1.w = acc[i][7] + bia[7] + r1.w;
        float4* dst = (float4*)(Xout + (size_t)(row0 + i) * DIM + col0);
        dst[0] = o0;
        dst[1] = o1;
    }
}

// ---------------- launcher ----------------
extern "C" void kernel_launch(void* const* d_in, const int* in_sizes, int n_in,
                              void* d_out, int out_size) {
    const float* feats = (const float*)d_in[0];
    const float* w_dw  = (const float*)d_in[1];   // (2,49,128)
    const float* b_dw  = (const float*)d_in[2];   // (2,128)
    const float* ln_g  = (const float*)d_in[3];   // (2,128)
    const float* ln_b  = (const float*)d_in[4];   // (2,128)
    const float* w1    = (const float*)d_in[5];   // (2,128,512)
    const float* b1    = (const float*)d_in[6];   // (2,512)
    const float* grn_g = (const float*)d_in[7];   // (2,512)
    const float* grn_b = (const float*)d_in[8];   // (2,512)
    const float* w2    = (const float*)d_in[9];   // (2,512,128)
    const float* b2    = (const float*)d_in[10];  // (2,128)
    const int*   nbr   = (const int*)d_in[11];    // (N,49)
    float* out = (float*)d_out;

    dim3 g1(MBLK, 4), g2(MBLK, 1);
    for (int d = 0; d < 2; d++) {
        dwconv_ln_kernel<<<NPTS / PTS, 128>>>(
            feats, nbr, w_dw + (size_t)d * KK * DIM, b_dw + d * DIM,
            ln_g + d * DIM, ln_b + d * DIM, d);
        gemm1_gelu_kernel<<<g1, 256>>>(
            w1 + (size_t)d * DIM * HID, b1 + d * HID);
        grn_scale_kernel<<<1, HID>>>(grn_g + d * HID);
        gemm2_resid_kernel<<<g2, 256>>>(
            w2 + (size_t)d * HID * DIM, b2 + d * DIM,
            grn_b + d * HID, feats, out, d);
    }
}

// round 3
// speedup vs baseline: 2.4662x; 2.4662x over previous
#include <cuda_runtime.h>
#include <math.h>
#include <stdint.h>

#define NPTS 160000
#define DIM  128
#define HID  512
#define KK   49
#define MBLK 1250   /* NPTS / 128 */

// ---------------- scratch (device globals; no allocations) ----------------
__device__ float g_xln[(size_t)NPTS * DIM];
__device__ float g_h[(size_t)NPTS * HID];
__device__ float g_part[MBLK * HID];
__device__ float g_s[HID];
__device__ float g_b2s[DIM];
__device__ float g_w2s[HID * DIM];
__device__ float g_x1[(size_t)NPTS * DIM];

// ---------------- helpers ----------------
__device__ __forceinline__ uint32_t f2tf(float f) {
    uint32_t r; asm("cvt.rna.tf32.f32 %0, %1;" : "=r"(r) : "f"(f)); return r;
}
__device__ __forceinline__ void mma8(float* c, const uint32_t* a, const uint32_t* b) {
    asm volatile(
        "mma.sync.aligned.m16n8k8.row.col.f32.tf32.tf32.f32 "
        "{%0,%1,%2,%3},{%4,%5,%6,%7},{%8,%9},{%0,%1,%2,%3};"
        : "+f"(c[0]), "+f"(c[1]), "+f"(c[2]), "+f"(c[3])
        : "r"(a[0]), "r"(a[1]), "r"(a[2]), "r"(a[3]), "r"(b[0]), "r"(b[1]));
}
#define CPA16(dst, src) \
    asm volatile("cp.async.cg.shared.global [%0], [%1], 16;\n" :: "r"(dst), "l"(src))
__device__ __forceinline__ float gelu_f(float x) {
    return 0.5f * x * (1.0f + erff(x * 0.7071067811865476f));
}

// ---------------- dwconv (sparse 7x7 depthwise) + LayerNorm ----------------
// warp per point, lane = 4 channels (float4); shfl-only LN; no inner barriers.
__global__ __launch_bounds__(256) void dwconv_ln_kernel(
    const float* __restrict__ feats, const int* __restrict__ nbr,
    const float* __restrict__ w, const float* __restrict__ bdw,
    const float* __restrict__ lg, const float* __restrict__ lb,
    const float* __restrict__ xln_out_dummy, int depth)
{
    __shared__ float sw[KK * DIM];
    __shared__ int   snbr[8 * KK];
    const float* X = depth ? g_x1 : feats;
    const int tid = threadIdx.x;
    for (int i = tid; i < KK * DIM; i += 256) sw[i] = w[i];
    const int p0 = blockIdx.x * 8;
    for (int i = tid; i < 8 * KK; i += 256) snbr[i] = nbr[(size_t)p0 * KK + i];
    const int wid = tid >> 5, lane = tid & 31;
    const float4 bd = ((const float4*)bdw)[lane];
    const float4 gg = ((const float4*)lg)[lane];
    const float4 bb = ((const float4*)lb)[lane];
    __syncthreads();

    const int pt = p0 + wid;
    float4 acc = bd;
    const float4* X4 = (const float4*)X;
    for (int k = 0; k < KK; k++) {
        int idx = snbr[wid * KK + k];           // uniform per warp
        if (idx < NPTS) {
            float4 x = __ldg(X4 + (size_t)idx * 32 + lane);
            const float4 wv = *(const float4*)(sw + k * DIM + lane * 4);
            acc.x += x.x * wv.x; acc.y += x.y * wv.y;
            acc.z += x.z * wv.z; acc.w += x.w * wv.w;
        }
    }
    float s = acc.x + acc.y + acc.z + acc.w;
    #pragma unroll
    for (int o = 16; o > 0; o >>= 1) s += __shfl_xor_sync(0xffffffffu, s, o);
    float mu = s * (1.0f / DIM);
    float4 d = make_float4(acc.x - mu, acc.y - mu, acc.z - mu, acc.w - mu);
    float v = d.x * d.x + d.y * d.y + d.z * d.z + d.w * d.w;
    #pragma unroll
    for (int o = 16; o > 0; o >>= 1) v += __shfl_xor_sync(0xffffffffu, v, o);
    float inv = rsqrtf(v * (1.0f / DIM) + 1e-6f);
    float4 y = make_float4(d.x * inv * gg.x + bb.x, d.y * inv * gg.y + bb.y,
                           d.z * inv * gg.z + bb.z, d.w * inv * gg.w + bb.w);
    ((float4*)g_xln)[(size_t)pt * 32 + lane] = y;
}

// ---------------- tf32 tensor-core GEMM, 128x128 CTA, 64x32 warp tiles ----
// EPI=1: Out=gelu(A@B+bias) -> g_h, + column-sumsq partials -> g_part
// EPI=2: Out = A@B + bias + Xin  (GRN pre-folded into B=g_w2s, bias=g_b2s)
template<int KTOT, int NB, int EPI>
__global__ __launch_bounds__(256, 2) void gemm_tf32(
    const float* __restrict__ A, const float* __restrict__ B,
    const float* __restrict__ bias, const float* __restrict__ Xin,
    float* __restrict__ Out, float* __restrict__ part)
{
    constexpr int LDA = 20, LDB = 136, KS = 16, NSTEP = KTOT / KS;
    __shared__ float As[2][128 * LDA];
    __shared__ float Bs[2][KS * LDB];
    __shared__ float s_cq[128];

    const int tid = threadIdx.x;
    const int bm = blockIdx.x * 128;
    const int bn = blockIdx.y * 128;
    if (EPI == 1 && tid < 128) s_cq[tid] = 0.0f;

    const int w = tid >> 5, lane = tid & 31;
    const int l4 = lane >> 2, lm4 = lane & 3;
    const int wm = (w & 1) * 64, wn = (w >> 1) * 32;

    const float* Ag = A + (size_t)bm * KTOT;
    const float* Bg = B + bn;

    float acc[4][4][4] = {};

    // --- async load helpers: 512 16B-chunks per tile, 2 per thread ---
    #define LOAD_A(st, k0) { \
        _Pragma("unroll") \
        for (int i = 0; i < 2; i++) { \
            int c = tid + i * 256; \
            int r = c >> 2, cc = (c & 3) * 4; \
            uint32_t dst = (uint32_t)__cvta_generic_to_shared(&As[st][r * LDA + cc]); \
            CPA16(dst, Ag + (size_t)r * KTOT + (k0) + cc); \
        } }
    #define LOAD_B(st, k0) { \
        _Pragma("unroll") \
        for (int i = 0; i < 2; i++) { \
            int c = tid + i * 256; \
            int r = c >> 5, cc = (c & 31) * 4; \
            uint32_t dst = (uint32_t)__cvta_generic_to_shared(&Bs[st][r * LDB + cc]); \
            CPA16(dst, Bg + (size_t)((k0) + r) * NB + cc); \
        } }

    LOAD_A(0, 0); LOAD_B(0, 0);
    asm volatile("cp.async.commit_group;\n");

    for (int s = 0; s < NSTEP; s++) {
        if (s + 1 < NSTEP) {
            LOAD_A((s + 1) & 1, (s + 1) * KS);
            LOAD_B((s + 1) & 1, (s + 1) * KS);
            asm volatile("cp.async.commit_group;\n");
            asm volatile("cp.async.wait_group 1;\n");
        } else {
            asm volatile("cp.async.wait_group 0;\n");
        }
        __syncthreads();
        const float* As_ = As[s & 1];
        const float* Bs_ = Bs[s & 1];
        #pragma unroll
        for (int kb = 0; kb < 2; kb++) {
            uint32_t af[4][4], bf[4][2];
            #pragma unroll
            for (int mt = 0; mt < 4; mt++) {
                const float* p = As_ + (wm + mt * 16 + l4) * LDA + kb * 8 + lm4;
                af[mt][0] = f2tf(p[0]);
                af[mt][1] = f2tf(p[8 * LDA]);
                af[mt][2] = f2tf(p[4]);
                af[mt][3] = f2tf(p[8 * LDA + 4]);
            }
            #pragma unroll
            for (int nt = 0; nt < 4; nt++) {
                const float* q = Bs_ + (kb * 8 + lm4) * LDB + wn + nt * 8 + l4;
                bf[nt][0] = f2tf(q[0]);
                bf[nt][1] = f2tf(q[4 * LDB]);
            }
            #pragma unroll
            for (int mt = 0; mt < 4; mt++)
                #pragma unroll
                for (int nt = 0; nt < 4; nt++)
                    mma8(acc[mt][nt], af[mt], bf[nt]);
        }
        __syncthreads();
    }
    #undef LOAD_A
    #undef LOAD_B

    // ---------------- epilogue ----------------
    if (EPI == 1) {
        float cq[4][2] = {};
        #pragma unroll
        for (int mt = 0; mt < 4; mt++) {
            int r0 = bm + wm + mt * 16 + l4;
            #pragma unroll
            for (int nt = 0; nt < 4; nt++) {
                int c = bn + wn + nt * 8 + lm4 * 2;
                float b0 = __ldg(bias + c), b1 = __ldg(bias + c + 1);
                float t0 = gelu_f(acc[mt][nt][0] + b0);
                float t1 = gelu_f(acc[mt][nt][1] + b1);
                float t2 = gelu_f(acc[mt][nt][2] + b0);
                float t3 = gelu_f(acc[mt][nt][3] + b1);
                *(float2*)(Out + (size_t)r0 * NB + c)       = make_float2(t0, t1);
                *(float2*)(Out + (size_t)(r0 + 8) * NB + c) = make_float2(t2, t3);
                cq[nt][0] += t0 * t0 + t2 * t2;
                cq[nt][1] += t1 * t1 + t3 * t3;
            }
        }
        #pragma unroll
        for (int nt = 0; nt < 4; nt++)
            #pragma unroll
            for (int j = 0; j < 2; j++) {
                float v = cq[nt][j];
                v += __shfl_xor_sync(0xffffffffu, v, 16);
                v += __shfl_xor_sync(0xffffffffu, v, 8);
                v += __shfl_xor_sync(0xffffffffu, v, 4);
                if (l4 == 0) atomicAdd(&s_cq[wn + nt * 8 + lm4 * 2 + j], v);
            }
        __syncthreads();
        if (tid < 128) part[blockIdx.x * HID + bn + tid] = s_cq[tid];
    } else {
        #pragma unroll
        for (int mt = 0; mt < 4; mt++) {
            int r0 = bm + wm + mt * 16 + l4;
            #pragma unroll
            for (int nt = 0; nt < 4; nt++) {
                int c = bn + wn + nt * 8 + lm4 * 2;
                float b0 = __ldg(bias + c), b1 = __ldg(bias + c + 1);
                float2 x0 = *(const float2*)(Xin + (size_t)r0 * NB + c);
                float2 x1 = *(const float2*)(Xin + (size_t)(r0 + 8) * NB + c);
                *(float2*)(Out + (size_t)r0 * NB + c) =
                    make_float2(acc[mt][nt][0] + b0 + x0.x, acc[mt][nt][1] + b1 + x0.y);
                *(float2*)(Out + (size_t)(r0 + 8) * NB + c) =
                    make_float2(acc[mt][nt][2] + b0 + x1.x, acc[mt][nt][3] + b1 + x1.y);
            }
        }
    }
}

// ---------------- GRN prep: s[k]=g*nx+1; b2' = b2 + grn_b @ W2 ------------
__global__ void grn_prep_kernel(const float* __restrict__ grn_g,
                                const float* __restrict__ grn_b,
                                const float* __restrict__ W2,
                                const float* __restrict__ b2)
{
    const int j = threadIdx.x;   // 512 threads, 1 block
    float sum = 0.0f;
    for (int r = 0; r < MBLK; r++) sum += g_part[r * HID + j];
    float gx = sqrtf(sum);
    __shared__ float sm[HID];
    sm[j] = gx;
    __syncthreads();
    for (int o = 256; o > 0; o >>= 1) {
        if (j < o) sm[j] += sm[j + o];
        __syncthreads();
    }
    float mean = sm[0] * (1.0f / HID);
    g_s[j] = __ldg(grn_g + j) * (gx / (mean + 1e-6f)) + 1.0f;
    if (j < DIM) {
        float acc = __ldg(b2 + j);
        for (int k = 0; k < HID; k++)
            acc += __ldg(grn_b + k) * __ldg(W2 + (size_t)k * DIM + j);
        g_b2s[j] = acc;
    }
}

// ---------------- W2' = diag(s) * W2 --------------------------------------
__global__ void scale_w2_kernel(const float* __restrict__ W2)
{
    int i = blockIdx.x * blockDim.x + threadIdx.x;  // 16384 float4s
    float4 wv = ((const float4*)W2)[i];
    float s = g_s[i >> 5];
    ((float4*)g_w2s)[i] = make_float4(wv.x * s, wv.y * s, wv.z * s, wv.w * s);
}

// ---------------- launcher ----------------
extern "C" void kernel_launch(void* const* d_in, const int* in_sizes, int n_in,
                              void* d_out, int out_size) {
    const float* feats = (const float*)d_in[0];
    const float* w_dw  = (const float*)d_in[1];
    const float* b_dw  = (const float*)d_in[2];
    const float* ln_g  = (const float*)d_in[3];
    const float* ln_b  = (const float*)d_in[4];
    const float* w1    = (const float*)d_in[5];
    const float* b1    = (const float*)d_in[6];
    const float* grn_g = (const float*)d_in[7];
    const float* grn_b = (const float*)d_in[8];
    const float* w2    = (const float*)d_in[9];
    const float* b2    = (const float*)d_in[10];
    const int*   nbr   = (const int*)d_in[11];
    float* out = (float*)d_out;

    float *p_xln, *p_h, *p_part, *p_w2s, *p_b2s, *p_x1;
    cudaGetSymbolAddress((void**)&p_xln,  g_xln);
    cudaGetSymbolAddress((void**)&p_h,    g_h);
    cudaGetSymbolAddress((void**)&p_part, g_part);
    cudaGetSymbolAddress((void**)&p_w2s,  g_w2s);
    cudaGetSymbolAddress((void**)&p_b2s,  g_b2s);
    cudaGetSymbolAddress((void**)&p_x1,   g_x1);

    for (int d = 0; d < 2; d++) {
        dwconv_ln_kernel<<<NPTS / 8, 256>>>(
            feats, nbr, w_dw + (size_t)d * KK * DIM, b_dw + d * DIM,
            ln_g + d * DIM, ln_b + d * DIM, p_xln, d);
        gemm_tf32<DIM, HID, 1><<<dim3(MBLK, 4), 256>>>(
            p_xln, w1 + (size_t)d * DIM * HID, b1 + d * HID,
            (const float*)0, p_h, p_part);
        grn_prep_kernel<<<1, HID>>>(grn_g + d * HID, grn_b + d * HID,
                                    w2 + (size_t)d * HID * DIM, b2 + d * DIM);
        scale_w2_kernel<<<64, 256>>>(w2 + (size_t)d * HID * DIM);
        const float* Xin = d ? p_x1 : feats;
        float* Xout = d ? out : p_x1;
        gemm_tf32<HID, DIM, 2><<<dim3(MBLK, 1), 256>>>(
            p_h, p_w2s, p_b2s, Xin, Xout, (float*)0);
    }
}

// round 5
// speedup vs baseline: 3.0870x; 1.2517x over previous
#include <cuda_runtime.h>
#include <cuda_bf16.h>
#include <math.h>
#include <stdint.h>

#define NPTS 160000
#define DIM  128
#define HID  512
#define KK   49
#define MBLK 1250   /* NPTS / 128 */

// ---------------- scratch (device globals; no allocations) ----------------
__device__ __nv_bfloat16 g_xln[(size_t)NPTS * DIM];
__device__ __nv_bfloat16 g_h[(size_t)NPTS * HID];
__device__ float g_part[MBLK * HID];
__device__ float g_gx[HID];
__device__ float g_s[HID];
__device__ float g_b2s[DIM];
__device__ __nv_bfloat16 g_w1t[HID * DIM];   // w1 transposed [n][k], bf16
__device__ __nv_bfloat16 g_w2t[DIM * HID];   // s*w2 transposed [n][k], bf16
__device__ float g_x1[(size_t)NPTS * DIM];

// ---------------- helpers ----------------
__device__ __forceinline__ void mma16(float* c, const uint32_t* a, const uint32_t* b) {
    asm volatile(
        "mma.sync.aligned.m16n8k16.row.col.f32.bf16.bf16.f32 "
        "{%0,%1,%2,%3},{%4,%5,%6,%7},{%8,%9},{%0,%1,%2,%3};"
        : "+f"(c[0]), "+f"(c[1]), "+f"(c[2]), "+f"(c[3])
        : "r"(a[0]), "r"(a[1]), "r"(a[2]), "r"(a[3]), "r"(b[0]), "r"(b[1]));
}
#define CPA16(dst, src) \
    asm volatile("cp.async.cg.shared.global [%0], [%1], 16;\n" :: "r"(dst), "l"(src))
__device__ __forceinline__ float gelu_f(float x) {
    return 0.5f * x * (1.0f + erff(x * 0.7071067811865476f));
}

// ---------------- dwconv (sparse 7x7 depthwise) + LayerNorm -> bf16 -------
__global__ __launch_bounds__(256) void dwconv_ln_kernel(
    const float* __restrict__ feats, const int* __restrict__ nbr,
    const float* __restrict__ w, const float* __restrict__ bdw,
    const float* __restrict__ lg, const float* __restrict__ lb, int depth)
{
    __shared__ float sw[KK * DIM];
    __shared__ int   snbr[8 * KK];
    const float* X = depth ? g_x1 : feats;
    const int tid = threadIdx.x;
    for (int i = tid; i < KK * DIM; i += 256) sw[i] = w[i];
    const int p0 = blockIdx.x * 8;
    for (int i = tid; i < 8 * KK; i += 256) snbr[i] = nbr[(size_t)p0 * KK + i];
    const int wid = tid >> 5, lane = tid & 31;
    const float4 bd = ((const float4*)bdw)[lane];
    const float4 gg = ((const float4*)lg)[lane];
    const float4 bb = ((const float4*)lb)[lane];
    __syncthreads();

    const int pt = p0 + wid;
    float4 acc = bd;
    const float4* X4 = (const float4*)X;
    for (int k = 0; k < KK; k++) {
        int idx = snbr[wid * KK + k];           // uniform per warp
        if (idx < NPTS) {
            float4 x = __ldg(X4 + (size_t)idx * 32 + lane);
            const float4 wv = *(const float4*)(sw + k * DIM + lane * 4);
            acc.x += x.x * wv.x; acc.y += x.y * wv.y;
            acc.z += x.z * wv.z; acc.w += x.w * wv.w;
        }
    }
    float s = acc.x + acc.y + acc.z + acc.w;
    #pragma unroll
    for (int o = 16; o > 0; o >>= 1) s += __shfl_xor_sync(0xffffffffu, s, o);
    float mu = s * (1.0f / DIM);
    float4 d = make_float4(acc.x - mu, acc.y - mu, acc.z - mu, acc.w - mu);
    float v = d.x * d.x + d.y * d.y + d.z * d.z + d.w * d.w;
    #pragma unroll
    for (int o = 16; o > 0; o >>= 1) v += __shfl_xor_sync(0xffffffffu, v, o);
    float inv = rsqrtf(v * (1.0f / DIM) + 1e-6f);
    __nv_bfloat162 y01 = make_bfloat162(
        __float2bfloat16(d.x * inv * gg.x + bb.x),
        __float2bfloat16(d.y * inv * gg.y + bb.y));
    __nv_bfloat162 y23 = make_bfloat162(
        __float2bfloat16(d.z * inv * gg.z + bb.z),
        __float2bfloat16(d.w * inv * gg.w + bb.w));
    __nv_bfloat162* dst = (__nv_bfloat162*)g_xln + (size_t)pt * 64 + lane * 2;
    dst[0] = y01; dst[1] = y23;
}

// ---------------- transpose (+optional per-k scale) fp32[K][N]->bf16[N][K] -
__global__ void tr_bf16_kernel(const float* __restrict__ src,
                               __nv_bfloat16* __restrict__ dst,
                               const float* __restrict__ scale,
                               int K, int Nn)
{
    __shared__ float t[32][33];
    const int kb = blockIdx.x * 32, nb = blockIdx.y * 32;
    for (int r = threadIdx.y; r < 32; r += 8) {
        float v = src[(size_t)(kb + r) * Nn + nb + threadIdx.x];
        if (scale) v *= __ldg(scale + kb + r);
        t[r][threadIdx.x] = v;
    }
    __syncthreads();
    for (int r = threadIdx.y; r < 32; r += 8)
        dst[(size_t)(nb + r) * K + kb + threadIdx.x] =
            __float2bfloat16(t[threadIdx.x][r]);
}

// ---------------- bf16 tensor-core GEMM, 128x128 CTA, 64x32 warp tiles ----
// A bf16 [M][KTOT] row-major; Bt bf16 [N][KTOT] (n-major).
// EPI=1: g_h = bf16(gelu(A@B+bias)), column-sumsq partials -> part
// EPI=2: Out = A@B + bias + Xin (fp32)
template<int KTOT, int NB, int EPI>
__global__ __launch_bounds__(256, 2) void gemm_bf16(
    const __nv_bfloat16* __restrict__ A, const __nv_bfloat16* __restrict__ Bt,
    const float* __restrict__ bias, const float* __restrict__ Xin,
    float* __restrict__ Out, float* __restrict__ part)
{
    constexpr int LDS32 = 20;          // b32 pitch per 32-element bf16 row (pad)
    constexpr int KS = 32, NSTEP = KTOT / KS;
    __shared__ uint32_t As[2][128 * LDS32];
    __shared__ uint32_t Bs[2][128 * LDS32];
    __shared__ float s_cq[128];

    const int tid = threadIdx.x;
    const int bm = blockIdx.x * 128;
    const int bn = blockIdx.y * 128;
    if (EPI == 1 && tid < 128) s_cq[tid] = 0.0f;

    const int w = tid >> 5, lane = tid & 31;
    const int l4 = lane >> 2, lm4 = lane & 3;
    const int wm = (w & 1) * 64, wn = (w >> 1) * 32;

    const __nv_bfloat16* Ag = A + (size_t)bm * KTOT;
    const __nv_bfloat16* Bg = Bt + (size_t)bn * KTOT;

    float acc[4][4][4] = {};

    // 512 16B-chunks per tile (128 rows x 4 chunks), 2 per thread
    #define LOAD_T(sm, st, G, k0) { \
        _Pragma("unroll") \
        for (int i = 0; i < 2; i++) { \
            int c = tid + i * 256; \
            int r = c >> 2, ch = c & 3; \
            uint32_t dst = (uint32_t)__cvta_generic_to_shared( \
                &sm[st][r * LDS32 + ch * 4]); \
            CPA16(dst, G + (size_t)r * KTOT + (k0) + ch * 8); \
        } }

    LOAD_T(As, 0, Ag, 0); LOAD_T(Bs, 0, Bg, 0);
    asm volatile("cp.async.commit_group;\n");

    for (int s = 0; s < NSTEP; s++) {
        if (s + 1 < NSTEP) {
            LOAD_T(As, (s + 1) & 1, Ag, (s + 1) * KS);
            LOAD_T(Bs, (s + 1) & 1, Bg, (s + 1) * KS);
            asm volatile("cp.async.commit_group;\n");
            asm volatile("cp.async.wait_group 1;\n");
        } else {
            asm volatile("cp.async.wait_group 0;\n");
        }
        __syncthreads();
        const uint32_t* As_ = As[s & 1];
        const uint32_t* Bs_ = Bs[s & 1];
        #pragma unroll
        for (int kb = 0; kb < 2; kb++) {
            uint32_t af[4][4], bf[4][2];
            #pragma unroll
            for (int mt = 0; mt < 4; mt++) {
                const uint32_t* p = As_ + (wm + mt * 16 + l4) * LDS32 + kb * 8 + lm4;
                af[mt][0] = p[0];
                af[mt][1] = p[8 * LDS32];
                af[mt][2] = p[4];
                af[mt][3] = p[8 * LDS32 + 4];
            }
            #pragma unroll
            for (int nt = 0; nt < 4; nt++) {
                const uint32_t* q = Bs_ + (wn + nt * 8 + l4) * LDS32 + kb * 8 + lm4;
                bf[nt][0] = q[0];
                bf[nt][1] = q[4];
            }
            #pragma unroll
            for (int mt = 0; mt < 4; mt++)
                #pragma unroll
                for (int nt = 0; nt < 4; nt++)
                    mma16(acc[mt][nt], af[mt], bf[nt]);
        }
        __syncthreads();
    }
    #undef LOAD_T

    // ---------------- epilogue ----------------
    if (EPI == 1) {
        float cq[4][2] = {};
        #pragma unroll
        for (int mt = 0; mt < 4; mt++) {
            int r0 = bm + wm + mt * 16 + l4;
            #pragma unroll
            for (int nt = 0; nt < 4; nt++) {
                int c = bn + wn + nt * 8 + lm4 * 2;
                float b0 = __ldg(bias + c), b1 = __ldg(bias + c + 1);
                float t0 = gelu_f(acc[mt][nt][0] + b0);
                float t1 = gelu_f(acc[mt][nt][1] + b1);
                float t2 = gelu_f(acc[mt][nt][2] + b0);
                float t3 = gelu_f(acc[mt][nt][3] + b1);
                *((__nv_bfloat162*)(g_h + (size_t)r0 * NB + c)) =
                    make_bfloat162(__float2bfloat16(t0), __float2bfloat16(t1));
                *((__nv_bfloat162*)(g_h + (size_t)(r0 + 8) * NB + c)) =
                    make_bfloat162(__float2bfloat16(t2), __float2bfloat16(t3));
                cq[nt][0] += t0 * t0 + t2 * t2;
                cq[nt][1] += t1 * t1 + t3 * t3;
            }
        }
        #pragma unroll
        for (int nt = 0; nt < 4; nt++)
            #pragma unroll
            for (int j = 0; j < 2; j++) {
                float v = cq[nt][j];
                v += __shfl_xor_sync(0xffffffffu, v, 16);
                v += __shfl_xor_sync(0xffffffffu, v, 8);
                v += __shfl_xor_sync(0xffffffffu, v, 4);
                if (l4 == 0) atomicAdd(&s_cq[wn + nt * 8 + lm4 * 2 + j], v);
            }
        __syncthreads();
        if (tid < 128) part[blockIdx.x * HID + bn + tid] = s_cq[tid];
    } else {
        #pragma unroll
        for (int mt = 0; mt < 4; mt++) {
            int r0 = bm + wm + mt * 16 + l4;
            #pragma unroll
            for (int nt = 0; nt < 4; nt++) {
                int c = bn + wn + nt * 8 + lm4 * 2;
                float b0 = __ldg(bias + c), b1 = __ldg(bias + c + 1);
                float2 x0 = *(const float2*)(Xin + (size_t)r0 * NB + c);
                float2 x1 = *(const float2*)(Xin + (size_t)(r0 + 8) * NB + c);
                *(float2*)(Out + (size_t)r0 * NB + c) =
                    make_float2(acc[mt][nt][0] + b0 + x0.x, acc[mt][nt][1] + b1 + x0.y);
                *(float2*)(Out + (size_t)(r0 + 8) * NB + c) =
                    make_float2(acc[mt][nt][2] + b0 + x1.x, acc[mt][nt][3] + b1 + x1.y);
            }
        }
    }
}

// ---------------- GRN column reduce: gx[j] = sqrt(sum_r part[r][j]) -------
__global__ void reduce_gx_kernel()
{
    __shared__ float sm[256];
    const int j0 = blockIdx.x * 128;               // 4 blocks x 128 cols
    const int t = threadIdx.x;
    const int j = j0 + (t & 127), half = t >> 7;
    float sum = 0.0f;
    for (int r = half; r < MBLK; r += 2) sum += g_part[r * HID + j];
    sm[t] = sum;
    __syncthreads();
    if (t < 128) g_gx[j0 + t] = sqrtf(sm[t] + sm[t + 128]);
}

// ---------------- GRN finalize: s[k], b2' = b2 + grn_b @ W2 ---------------
__global__ void grn_finalize_kernel(const float* __restrict__ grn_g,
                                    const float* __restrict__ grn_b,
                                    const float* __restrict__ W2,
                                    const float* __restrict__ b2)
{
    const int j = threadIdx.x;   // 512 threads, 1 block
    __shared__ float sm[HID];
    __shared__ float sgb[HID];
    float gx = g_gx[j];
    sm[j] = gx;
    sgb[j] = __ldg(grn_b + j);
    __syncthreads();
    for (int o = 256; o > 0; o >>= 1) {
        if (j < o) sm[j] += sm[j + o];
        __syncthreads();
    }
    float mean = sm[0] * (1.0f / HID);
    g_s[j] = __ldg(grn_g + j) * (gx / (mean + 1e-6f)) + 1.0f;
    if (j < DIM) {
        float acc = __ldg(b2 + j);
        #pragma unroll 8
        for (int k = 0; k < HID; k++)
            acc += sgb[k] * __ldg(W2 + (size_t)k * DIM + j);
        g_b2s[j] = acc;
    }
}

// ---------------- launcher ----------------
extern "C" void kernel_launch(void* const* d_in, const int* in_sizes, int n_in,
                              void* d_out, int out_size) {
    const float* feats = (const float*)d_in[0];
    const float* w_dw  = (const float*)d_in[1];
    const float* b_dw  = (const float*)d_in[2];
    const float* ln_g  = (const float*)d_in[3];
    const float* ln_b  = (const float*)d_in[4];
    const float* w1    = (const float*)d_in[5];
    const float* b1    = (const float*)d_in[6];
    const float* grn_g = (const float*)d_in[7];
    const float* grn_b = (const float*)d_in[8];
    const float* w2    = (const float*)d_in[9];
    const float* b2    = (const float*)d_in[10];
    const int*   nbr   = (const int*)d_in[11];
    float* out = (float*)d_out;

    __nv_bfloat16 *p_xln, *p_h, *p_w1t, *p_w2t;
    float *p_part, *p_b2s, *p_x1, *p_s;
    cudaGetSymbolAddress((void**)&p_xln,  g_xln);
    cudaGetSymbolAddress((void**)&p_h,    g_h);
    cudaGetSymbolAddress((void**)&p_part, g_part);
    cudaGetSymbolAddress((void**)&p_w1t,  g_w1t);
    cudaGetSymbolAddress((void**)&p_w2t,  g_w2t);
    cudaGetSymbolAddress((void**)&p_b2s,  g_b2s);
    cudaGetSymbolAddress((void**)&p_x1,   g_x1);
    cudaGetSymbolAddress((void**)&p_s,    g_s);

    dim3 tb(32, 8);
    for (int d = 0; d < 2; d++) {
        dwconv_ln_kernel<<<NPTS / 8, 256>>>(
            feats, nbr, w_dw + (size_t)d * KK * DIM, b_dw + d * DIM,
            ln_g + d * DIM, ln_b + d * DIM, d);
        tr_bf16_kernel<<<dim3(DIM / 32, HID / 32), tb>>>(
            w1 + (size_t)d * DIM * HID, p_w1t, (const float*)0, DIM, HID);
        gemm_bf16<DIM, HID, 1><<<dim3(MBLK, 4), 256>>>(
            p_xln, p_w1t, b1 + d * HID, (const float*)0, (float*)0, p_part);
        reduce_gx_kernel<<<4, 256>>>();
        grn_finalize_kernel<<<1, HID>>>(grn_g + d * HID, grn_b + d * HID,
                                        w2 + (size_t)d * HID * DIM, b2 + d * DIM);
        tr_bf16_kernel<<<dim3(HID / 32, DIM / 32), tb>>>(
            w2 + (size_t)d * HID * DIM, p_w2t, p_s, HID, DIM);
        const float* Xin = d ? p_x1 : feats;
        float* Xout = d ? out : p_x1;
        gemm_bf16<HID, DIM, 2><<<dim3(MBLK, 1), 256>>>(
            p_h, p_w2t, p_b2s, Xin, Xout, (float*)0);
    }
}

// round 7
// speedup vs baseline: 3.4289x; 1.1108x over previous
#include <cuda_runtime.h>
#include <cuda_bf16.h>
#include <math.h>
#include <stdint.h>

#define NPTS 160000
#define DIM  128
#define HID  512
#define KK   49
#define MBLK 1250   /* NPTS / 128 */

// ---------------- scratch (device globals; no allocations) ----------------
__device__ __nv_bfloat16 g_xln[(size_t)NPTS * DIM];
__device__ __nv_bfloat16 g_h[(size_t)NPTS * HID];
__device__ float g_part[(size_t)HID * MBLK];   // [col][rowblk]
__device__ float g_gx[HID];
__device__ float g_s[HID];
__device__ float g_b2s[DIM];
__device__ __nv_bfloat16 g_w1t[HID * DIM];   // w1 transposed [n][k], bf16
__device__ __nv_bfloat16 g_w2t[DIM * HID];   // s*w2 transposed [n][k], bf16
__device__ float g_x1[(size_t)NPTS * DIM];

// ---------------- helpers ----------------
__device__ __forceinline__ void mma16(float* c, const uint32_t* a, const uint32_t* b) {
    asm volatile(
        "mma.sync.aligned.m16n8k16.row.col.f32.bf16.bf16.f32 "
        "{%0,%1,%2,%3},{%4,%5,%6,%7},{%8,%9},{%0,%1,%2,%3};"
        : "+f"(c[0]), "+f"(c[1]), "+f"(c[2]), "+f"(c[3])
        : "r"(a[0]), "r"(a[1]), "r"(a[2]), "r"(a[3]), "r"(b[0]), "r"(b[1]));
}
__device__ __forceinline__ void ldsm4(uint32_t* d, uint32_t a) {
    asm volatile("ldmatrix.sync.aligned.m8n8.x4.shared.b16 {%0,%1,%2,%3},[%4];"
                 : "=r"(d[0]), "=r"(d[1]), "=r"(d[2]), "=r"(d[3]) : "r"(a));
}
__device__ __forceinline__ void ldsm2(uint32_t* d, uint32_t a) {
    asm volatile("ldmatrix.sync.aligned.m8n8.x2.shared.b16 {%0,%1},[%2];"
                 : "=r"(d[0]), "=r"(d[1]) : "r"(a));
}
#define CPA16(dst, src) \
    asm volatile("cp.async.cg.shared.global [%0], [%1], 16;\n" :: "r"(dst), "l"(src))
__device__ __forceinline__ float gelu_f(float x) {
    return 0.5f * x * (1.0f + erff(x * 0.7071067811865476f));
}

// ---------------- dwconv (sparse 7x7 depthwise) + LayerNorm -> bf16 -------
__global__ __launch_bounds__(256) void dwconv_ln_kernel(
    const float* __restrict__ feats, const int* __restrict__ nbr,
    const float* __restrict__ w, const float* __restrict__ bdw,
    const float* __restrict__ lg, const float* __restrict__ lb, int depth)
{
    __shared__ float sw[KK * DIM];
    __shared__ int   snbr[8 * KK];
    const float* X = depth ? g_x1 : feats;
    const int tid = threadIdx.x;
    for (int i = tid; i < KK * DIM; i += 256) sw[i] = w[i];
    const int p0 = blockIdx.x * 8;
    for (int i = tid; i < 8 * KK; i += 256) snbr[i] = nbr[(size_t)p0 * KK + i];
    const int wid = tid >> 5, lane = tid & 31;
    const float4 bd = ((const float4*)bdw)[lane];
    const float4 gg = ((const float4*)lg)[lane];
    const float4 bb = ((const float4*)lb)[lane];
    __syncthreads();

    const int pt = p0 + wid;
    float4 acc = bd;
    const float4* X4 = (const float4*)X;
    for (int k = 0; k < KK; k++) {
        int idx = snbr[wid * KK + k];           // uniform per warp
        if (idx < NPTS) {
            float4 x = __ldg(X4 + (size_t)idx * 32 + lane);
            const float4 wv = *(const float4*)(sw + k * DIM + lane * 4);
            acc.x += x.x * wv.x; acc.y += x.y * wv.y;
            acc.z += x.z * wv.z; acc.w += x.w * wv.w;
        }
    }
    float s = acc.x + acc.y + acc.z + acc.w;
    #pragma unroll
    for (int o = 16; o > 0; o >>= 1) s += __shfl_xor_sync(0xffffffffu, s, o);
    float mu = s * (1.0f / DIM);
    float4 d = make_float4(acc.x - mu, acc.y - mu, acc.z - mu, acc.w - mu);
    float v = d.x * d.x + d.y * d.y + d.z * d.z + d.w * d.w;
    #pragma unroll
    for (int o = 16; o > 0; o >>= 1) v += __shfl_xor_sync(0xffffffffu, v, o);
    float inv = rsqrtf(v * (1.0f / DIM) + 1e-6f);
    __nv_bfloat162 y01 = make_bfloat162(
        __float2bfloat16(d.x * inv * gg.x + bb.x),
        __float2bfloat16(d.y * inv * gg.y + bb.y));
    __nv_bfloat162 y23 = make_bfloat162(
        __float2bfloat16(d.z * inv * gg.z + bb.z),
        __float2bfloat16(d.w * inv * gg.w + bb.w));
    __nv_bfloat162* dst = (__nv_bfloat162*)g_xln + (size_t)pt * 64 + lane * 2;
    dst[0] = y01; dst[1] = y23;
}

// ---------------- transpose (+optional per-k scale) fp32[K][N]->bf16[N][K] -
__global__ void tr_bf16_kernel(const float* __restrict__ src,
                               __nv_bfloat16* __restrict__ dst,
                               const float* __restrict__ scale,
                               int K, int Nn)
{
    __shared__ float t[32][33];
    const int kb = blockIdx.x * 32, nb = blockIdx.y * 32;
    for (int r = threadIdx.y; r < 32; r += 8) {
        float v = src[(size_t)(kb + r) * Nn + nb + threadIdx.x];
        if (scale) v *= __ldg(scale + kb + r);
        t[r][threadIdx.x] = v;
    }
    __syncthreads();
    for (int r = threadIdx.y; r < 32; r += 8)
        dst[(size_t)(nb + r) * K + kb + threadIdx.x] =
            __float2bfloat16(t[threadIdx.x][r]);
}

// ---------------- bf16 tensor-core GEMM, 128x128 CTA, 64x32 warp tiles ----
// 3-stage cp.async pipeline, ldmatrix fragment loads.
// A bf16 [M][KTOT] row-major; Bt bf16 [N][KTOT] (n-major).
// EPI=1: g_h = bf16(gelu(A@B+bias)), column-sumsq partials -> part [col][blk]
// EPI=2: Out = A@B + bias + Xin (fp32)
template<int KTOT, int NB, int EPI>
__global__ __launch_bounds__(256, 2) void gemm_bf16(
    const __nv_bfloat16* __restrict__ A, const __nv_bfloat16* __restrict__ Bt,
    const float* __restrict__ bias, const float* __restrict__ Xin,
    float* __restrict__ Out, float* __restrict__ part)
{
    constexpr int LDS32 = 20;               // b32 pitch per 32-elem bf16 row
    constexpr int STG = 2560;               // u32 per stage per array
    constexpr int KS = 32, NSTEP = KTOT / KS;
    extern __shared__ uint32_t dsm[];
    uint32_t* As = dsm;
    uint32_t* Bs = dsm + 3 * STG;
    __shared__ float s_cq[128];

    const int tid = threadIdx.x;
    const int bm = blockIdx.x * 128;
    const int bn = blockIdx.y * 128;
    if (EPI == 1 && tid < 128) s_cq[tid] = 0.0f;

    const int w = tid >> 5, lane = tid & 31;
    const int l4 = lane >> 2, lm4 = lane & 3;
    const int wm = (w & 1) * 64, wn = (w >> 1) * 32;
    const int lr = lane & 7, seg = lane >> 3;
    const uint32_t offA = ((lr + (seg & 1) * 8) * LDS32 + (seg >> 1) * 4) * 4;
    const uint32_t offB = (lr * LDS32 + (seg & 1) * 4) * 4;

    const uint32_t As_sa = (uint32_t)__cvta_generic_to_shared(As);
    const uint32_t Bs_sa = (uint32_t)__cvta_generic_to_shared(Bs);

    const __nv_bfloat16* Ag = A + (size_t)bm * KTOT;
    const __nv_bfloat16* Bg = Bt + (size_t)bn * KTOT;

    float acc[4][4][4] = {};

    // 512 16B-chunks per tile (128 rows x 4 chunks), 2 per thread
    #define LOAD_T(base_sa, st, G, k0) { \
        _Pragma("unroll") \
        for (int i = 0; i < 2; i++) { \
            int c = tid + i * 256; \
            int r = c >> 2, ch = c & 3; \
            uint32_t dst = base_sa + (uint32_t)((st) * STG + r * LDS32 + ch * 4) * 4; \
            CPA16(dst, G + (size_t)r * KTOT + (k0) + ch * 8); \
        } }

    LOAD_T(As_sa, 0, Ag, 0); LOAD_T(Bs_sa, 0, Bg, 0);
    asm volatile("cp.async.commit_group;\n");
    LOAD_T(As_sa, 1, Ag, KS); LOAD_T(Bs_sa, 1, Bg, KS);
    asm volatile("cp.async.commit_group;\n");

    for (int s = 0; s < NSTEP; s++) {
        if (s + 2 < NSTEP) {
            int sl = (s + 2) % 3;
            LOAD_T(As_sa, sl, Ag, (s + 2) * KS);
            LOAD_T(Bs_sa, sl, Bg, (s + 2) * KS);
            asm volatile("cp.async.commit_group;\n");
            asm volatile("cp.async.wait_group 2;\n");
        } else if (s + 1 < NSTEP) {
            asm volatile("cp.async.wait_group 1;\n");
        } else {
            asm volatile("cp.async.wait_group 0;\n");
        }
        __syncthreads();
        const int cs = s % 3;
        const uint32_t As_st = As_sa + (uint32_t)cs * STG * 4;
        const uint32_t Bs_st = Bs_sa + (uint32_t)cs * STG * 4;
        #pragma unroll
        for (int kb = 0; kb < 2; kb++) {
            uint32_t af[4][4], bf[4][2];
            #pragma unroll
            for (int mt = 0; mt < 4; mt++)
                ldsm4(af[mt], As_st + (uint32_t)((wm + mt * 16) * LDS32 + kb * 8) * 4 + offA);
            #pragma unroll
            for (int nt = 0; nt < 4; nt++)
                ldsm2(bf[nt], Bs_st + (uint32_t)((wn + nt * 8) * LDS32 + kb * 8) * 4 + offB);
            #pragma unroll
            for (int mt = 0; mt < 4; mt++)
                #pragma unroll
                for (int nt = 0; nt < 4; nt++)
                    mma16(acc[mt][nt], af[mt], bf[nt]);
        }
        __syncthreads();
    }
    #undef LOAD_T

    // ---------------- epilogue ----------------
    if (EPI == 1) {
        float cq[4][2] = {};
        #pragma unroll
        for (int mt = 0; mt < 4; mt++) {
            int r0 = bm + wm + mt * 16 + l4;
            #pragma unroll
            for (int nt = 0; nt < 4; nt++) {
                int c = bn + wn + nt * 8 + lm4 * 2;
                float b0 = __ldg(bias + c), b1 = __ldg(bias + c + 1);
                float t0 = gelu_f(acc[mt][nt][0] + b0);
                float t1 = gelu_f(acc[mt][nt][1] + b1);
                float t2 = gelu_f(acc[mt][nt][2] + b0);
                float t3 = gelu_f(acc[mt][nt][3] + b1);
                *((__nv_bfloat162*)(g_h + (size_t)r0 * NB + c)) =
                    make_bfloat162(__float2bfloat16(t0), __float2bfloat16(t1));
                *((__nv_bfloat162*)(g_h + (size_t)(r0 + 8) * NB + c)) =
                    make_bfloat162(__float2bfloat16(t2), __float2bfloat16(t3));
                cq[nt][0] += t0 * t0 + t2 * t2;
                cq[nt][1] += t1 * t1 + t3 * t3;
            }
        }
        #pragma unroll
        for (int nt = 0; nt < 4; nt++)
            #pragma unroll
            for (int j = 0; j < 2; j++) {
                float v = cq[nt][j];
                v += __shfl_xor_sync(0xffffffffu, v, 16);
                v += __shfl_xor_sync(0xffffffffu, v, 8);
                v += __shfl_xor_sync(0xffffffffu, v, 4);
                if (l4 == 0) atomicAdd(&s_cq[wn + nt * 8 + lm4 * 2 + j], v);
            }
        __syncthreads();
        if (tid < 128)
            part[(size_t)(bn + tid) * MBLK + blockIdx.x] = s_cq[tid];
    } else {
        #pragma unroll
        for (int mt = 0; mt < 4; mt++) {
            int r0 = bm + wm + mt * 16 + l4;
            #pragma unroll
            for (int nt = 0; nt < 4; nt++) {
                int c = bn + wn + nt * 8 + lm4 * 2;
                float b0 = __ldg(bias + c), b1 = __ldg(bias + c + 1);
                float2 x0 = *(const float2*)(Xin + (size_t)r0 * NB + c);
                float2 x1 = *(const float2*)(Xin + (size_t)(r0 + 8) * NB + c);
                *(float2*)(Out + (size_t)r0 * NB + c) =
                    make_float2(acc[mt][nt][0] + b0 + x0.x, acc[mt][nt][1] + b1 + x0.y);
                *(float2*)(Out + (size_t)(r0 + 8) * NB + c) =
                    make_float2(acc[mt][nt][2] + b0 + x1.x, acc[mt][nt][3] + b1 + x1.y);
            }
        }
    }
}

// ---------------- GRN column reduce: gx[j] = sqrt(sum_r part[j][r]) -------
// one block per column; contiguous reads.
__global__ __launch_bounds__(256) void reduce_gx_kernel()
{
    const int j = blockIdx.x;
    float sum = 0.0f;
    for (int r = threadIdx.x; r < MBLK; r += 256)
        sum += g_part[(size_t)j * MBLK + r];
    #pragma unroll
    for (int o = 16; o > 0; o >>= 1) sum += __shfl_xor_sync(0xffffffffu, sum, o);
    __shared__ float sm[8];
    if ((threadIdx.x & 31) == 0) sm[threadIdx.x >> 5] = sum;
    __syncthreads();
    if (threadIdx.x == 0) {
        float t = 0.0f;
        #pragma unroll
        for (int i = 0; i < 8; i++) t += sm[i];
        g_gx[j] = sqrtf(t);
    }
}

// ---------------- GRN finalize: s[k], b2' = b2 + grn_b @ W2 ---------------
__global__ void grn_finalize_kernel(const float* __restrict__ grn_g,
                                    const float* __restrict__ grn_b,
                                    const float* __restrict__ W2,
                                    const float* __restrict__ b2)
{
    const int j = threadIdx.x;   // 512 threads, 1 block
    __shared__ float sm[HID];
    __shared__ float sgb[HID];
    float gx = g_gx[j];
    sm[j] = gx;
    sgb[j] = __ldg(grn_b + j);
    __syncthreads();
    for (int o = 256; o > 0; o >>= 1) {
        if (j < o) sm[j] += sm[j + o];
        __syncthreads();
    }
    float mean = sm[0] * (1.0f / HID);
    g_s[j] = __ldg(grn_g + j) * (gx / (mean + 1e-6f)) + 1.0f;
    if (j < DIM) {
        float acc = __ldg(b2 + j);
        #pragma unroll 8
        for (int k = 0; k < HID; k++)
            acc += sgb[k] * __ldg(W2 + (size_t)k * DIM + j);
        g_b2s[j] = acc;
    }
}

// ---------------- launcher ----------------
extern "C" void kernel_launch(void* const* d_in, const int* in_sizes, int n_in,
                              void* d_out, int out_size) {
    const float* feats = (const float*)d_in[0];
    const float* w_dw  = (const float*)d_in[1];
    const float* b_dw  = (const float*)d_in[2];
    const float* ln_g  = (const float*)d_in[3];
    const float* ln_b  = (const float*)d_in[4];
    const float* w1    = (const float*)d_in[5];
    const float* b1    = (const float*)d_in[6];
    const float* grn_g = (const float*)d_in[7];
    const float* grn_b = (const float*)d_in[8];
    const float* w2    = (const float*)d_in[9];
    const float* b2    = (const float*)d_in[10];
    const int*   nbr   = (const int*)d_in[11];
    float* out = (float*)d_out;

    __nv_bfloat16 *p_xln, *p_h, *p_w1t, *p_w2t;
    float *p_part, *p_b2s, *p_x1, *p_s;
    cudaGetSymbolAddress((void**)&p_xln,  g_xln);
    cudaGetSymbolAddress((void**)&p_h,    g_h);
    cudaGetSymbolAddress((void**)&p_part, g_part);
    cudaGetSymbolAddress((void**)&p_w1t,  g_w1t);
    cudaGetSymbolAddress((void**)&p_w2t,  g_w2t);
    cudaGetSymbolAddress((void**)&p_b2s,  g_b2s);
    cudaGetSymbolAddress((void**)&p_x1,   g_x1);
    cudaGetSymbolAddress((void**)&p_s,    g_s);

    const int SMEM_BYTES = 3 * 2560 * 2 * 4;   // 61440
    cudaFuncSetAttribute(gemm_bf16<DIM, HID, 1>,
                         cudaFuncAttributeMaxDynamicSharedMemorySize, SMEM_BYTES);
    cudaFuncSetAttribute(gemm_bf16<HID, DIM, 2>,
                         cudaFuncAttributeMaxDynamicSharedMemorySize, SMEM_BYTES);

    dim3 tb(32, 8);
    for (int d = 0; d < 2; d++) {
        dwconv_ln_kernel<<<NPTS / 8, 256>>>(
            feats, nbr, w_dw + (size_t)d * KK * DIM, b_dw + d * DIM,
            ln_g + d * DIM, ln_b + d * DIM, d);
        tr_bf16_kernel<<<dim3(DIM / 32, HID / 32), tb>>>(
            w1 + (size_t)d * DIM * HID, p_w1t, (const float*)0, DIM, HID);
        gemm_bf16<DIM, HID, 1><<<dim3(MBLK, 4), 256, SMEM_BYTES>>>(
            p_xln, p_w1t, b1 + d * HID, (const float*)0, (float*)0, p_part);
        reduce_gx_kernel<<<HID, 256>>>();
        grn_finalize_kernel<<<1, HID>>>(grn_g + d * HID, grn_b + d * HID,
                                        w2 + (size_t)d * HID * DIM, b2 + d * DIM);
        tr_bf16_kernel<<<dim3(HID / 32, DIM / 32), tb>>>(
            w2 + (size_t)d * HID * DIM, p_w2t, p_s, HID, DIM);
        const float* Xin = d ? p_x1 : feats;
        float* Xout = d ? out : p_x1;
        gemm_bf16<HID, DIM, 2><<<dim3(MBLK, 1), 256, SMEM_BYTES>>>(
            p_h, p_w2t, p_b2s, Xin, Xout, (float*)0);
    }
}